// round 16
// baseline (speedup 1.0000x reference)
#include <cuda_runtime.h>
#include <cstdint>

// Problem constants (fixed shapes)
#define THREADS      256
#define NROWS        512
#define NX           256
#define NQ           2048
#define RGRID        1024
#define SLOT_ELEMS   (NROWS * RGRID)      // 524288 floats per slot
#define NCOPY        9216                 // copy blocks (256 thr x 7 float4 each, exact)
#define COPY_HEAD    1024                 // copy blocks placed before compute blocks
#define GRID_BLOCKS  (NCOPY + NROWS)      // 9728
#define PER_THREAD   7                    // float4 per copy thread (exact division)
#define BLK_RANGE    (THREADS * PER_THREAD) // 1792 float4 = 28 KB contiguous per block

// math constants
#define K2F      (-72.13475204444817f)   /* -50 * log2(e) : exp(-50 d^2) = 2^(K2F*d^2) */
#define K2F2     (-144.26950408889634f)  /* 2 * K2F */
#define LOGC_F   (4.161530884690189f)    /* log(256) + log(0.1) + log(sqrt(2pi)) */
#define LOG2E_F  (1.4426950408889634f)
#define A_CONST  ((float)(-4.161530884690189 * 1.4426950408889634))  /* bias for phase A */
#define CUT_F    (160.0f)                /* very conservative: past denormal floor (-149) */
#define INVK_F   (0.013862943611198906f) /* 1 / 72.1347... = ln2/50 */
#define SLACK_F  (0.1f)                  /* absolute margin slack */
#define GSTEP_F  (0.03128054740957967f)  /* 32/1023 */

__device__ __forceinline__ float ex2f(float a) {
    float r;
    asm("ex2.approx.f32 %0, %1;" : "=f"(r) : "f"(a));
    return r;
}

__device__ __forceinline__ float wredmin(float v) {
    #pragma unroll
    for (int o = 16; o; o >>= 1) v = fminf(v, __shfl_xor_sync(0xffffffffu, v, o));
    return v;
}
__device__ __forceinline__ float wredmax(float v) {
    #pragma unroll
    for (int o = 16; o; o >>= 1) v = fmaxf(v, __shfl_xor_sync(0xffffffffu, v, o));
    return v;
}

// lower_bound over 256 sorted floats (branchless, 8 steps)
__device__ __forceinline__ int lbound(const float* __restrict__ xs, float v) {
    int p = 0;
    #pragma unroll
    for (int s = 128; s; s >>= 1)
        if (xs[p + s - 1] < v) p += s;
    return p;
}

__global__ __launch_bounds__(THREADS)
void kde_fused_kernel(
    const float* __restrict__ inputs,   // (256, 512)
    const float* __restrict__ bank,     // (128, 512, 1024)
    const float* __restrict__ noise,    // (512, 2048)
    const int*   __restrict__ comp,     // (512, 2048)
    const int*   __restrict__ sel_arr,  // (512)
    const int*   __restrict__ slot_ptr, // (1)
    float*       __restrict__ out)      // (128, 512, 1024)
{
    const int bid = blockIdx.x;
    const int tid = threadIdx.x;
    const int slot = slot_ptr[0];

    // Block placement (the R11/R14 layout -- best measured):
    //   [0, COPY_HEAD)                : copy (wave 1 saturates DRAM from t=0)
    //   [COPY_HEAD, COPY_HEAD+NROWS)  : compute (one confined band mid-kernel)
    //   [COPY_HEAD+NROWS, GRID_BLOCKS): copy (no compute tail)
    const bool is_compute = (bid >= COPY_HEAD) && (bid < COPY_HEAD + NROWS);

    if (is_compute) {
        // ============ COMPUTE PATH: one block per row ============
        // Warps 0-3 handle phase A (slot 0), warps 4-7 handle phase B (slot 1)
        // CONCURRENTLY; each warp covers 256 grid points (8 per thread), with
        // the geometric chain amortizing 2 MUFU over 8 points.
        const int r = bid - COPY_HEAD;
        __shared__ float xsh[NX];     // original order (for comp indexing)
        __shared__ float xsort[NX];   // sorted ascending (for range-culled sums)
        __shared__ float red[4][8];
        __shared__ int   sortok;

        const float xval = inputs[(size_t)tid * NROWS + r];
        xsh[tid]   = xval;
        xsort[tid] = xval;
        if (tid == 0) sortok = 1;
        __syncthreads();

        const int sel = sel_arr[r];

        // ---- per-row min/max of samples s and transformed y over 2048 q ----
        float smn = 3.4e38f, smx = -3.4e38f, ymn = 3.4e38f, ymx = -3.4e38f;
        const size_t rowq = (size_t)r * NQ;
        for (int q = tid; q < NQ; q += THREADS) {
            int   c = comp[rowq + q];
            float s = fmaf(0.1f, noise[rowq + q], xsh[c]);
            smn = fminf(smn, s);
            smx = fmaxf(smx, s);
            float y;
            if (sel == 0)      y = 2.0f * s;
            else if (sel == 1) y = s - 3.0f;
            else if (sel == 2) { float ss = (fabsf(s) < 1e-6f) ? 1e-6f : s; y = 1.0f / ss; }
            else if (sel == 3) y = 0.8f * s + 5.0f;
            else if (sel == 4) y = 1.0f / (1.0f + expf(-s));                        // sigmoid
            else               y = fmaxf(s, 0.0f) + log1pf(expf(-fabsf(s)));        // softplus
            ymn = fminf(ymn, y);
            ymx = fmaxf(ymx, y);
        }
        smn = wredmin(smn); smx = wredmax(smx);
        ymn = wredmin(ymn); ymx = wredmax(ymx);
        const int w = tid >> 5, l = tid & 31;
        if (l == 0) { red[0][w] = smn; red[1][w] = smx; red[2][w] = ymn; red[3][w] = ymx; }
        __syncthreads();
        smn = red[0][0]; smx = red[1][0]; ymn = red[2][0]; ymx = red[3][0];
        #pragma unroll
        for (int ww = 1; ww < 8; ww++) {
            smn = fminf(smn, red[0][ww]); smx = fmaxf(smx, red[1][ww]);
            ymn = fminf(ymn, red[2][ww]); ymx = fmaxf(ymx, red[3][ww]);
        }
        __syncthreads();  // everyone done reading red before sort mutates shared state

        // ---- bitonic sort xsort ascending (256 elements, 1 per thread) ----
        for (int kk = 2; kk <= NX; kk <<= 1) {
            for (int jj = kk >> 1; jj > 0; jj >>= 1) {
                int ixj = tid ^ jj;
                if (ixj > tid) {
                    float a = xsort[tid], b = xsort[ixj];
                    bool up = ((tid & kk) == 0);
                    if (up ? (a > b) : (a < b)) { xsort[tid] = b; xsort[ixj] = a; }
                }
                __syncthreads();
            }
        }

        // ---- verify sortedness; on any violation fall back to full range.
        if (tid < NX - 1) {
            if (xsort[tid] > xsort[tid + 1]) sortok = 0;  // benign write race
        }
        __syncthreads();
        const bool ok = (sortok != 0);

        const float dsA = smx - smn;
        const float dsB = ymx - ymn;
        const size_t rowo = (size_t)r * RGRID;

        const bool phA = (w < 4);
        const int  wp  = phA ? w : (w - 4);    // 0..3, covers j in [wp*256, wp*256+256)

        float loc[8], ap[8], acc[8];
        float mnv = 3.4e38f, mxv = -3.4e38f, apm = -3.4e38f;
        float bias = A_CONST;         // constant exp2 bias (A always; B if affine)
        bool  uniform = true;         // uniform spacing + constant bias -> chain OK
        float alpha = 1.0f;           // spacing multiplier for B

        if (phA) {
            #pragma unroll
            for (int k = 0; k < 8; k++) {
                const int j = wp * 256 + k * 32 + l;
                float tA = smn + dsA * ((float)j / 1023.0f);
                if (tA == 0.0f) tA = 1e-7f;
                loc[k] = tA;
                ap[k]  = A_CONST;
                mnv = fminf(mnv, tA); mxv = fmaxf(mxv, tA);
                acc[k] = 0.0f;
            }
            // analytic chunk bounds (loc monotonic in j up to zero-substitution)
            {
                float aLo = smn + dsA * ((float)(wp * 256) / 1023.0f);
                float aHi = smn + dsA * ((float)(wp * 256 + 255) / 1023.0f);
                mnv = fminf(mnv, fminf(aLo, aHi));
                mxv = fmaxf(mxv, fmaxf(aLo, aHi));
            }
            apm = A_CONST * 0.0f;     // phase-A margin uses A_CONST below
        } else {
            const bool affine = (sel == 0) | (sel == 1) | (sel == 3);
            alpha = (sel == 0) ? 0.5f : ((sel == 3) ? 1.25f : 1.0f);
            uniform = affine;
            #pragma unroll
            for (int k = 0; k < 8; k++) {
                const int j = wp * 256 + k * 32 + l;
                float t = ymn + dsB * ((float)j / 1023.0f);
                if (t == 0.0f) t = 1e-7f;

                float xi, ld;
                if (sel == 0)      { xi = t * 0.5f;          ld = -0.6931471805599453f; }
                else if (sel == 1) { xi = t + 3.0f;          ld = 0.0f; }
                else if (sel == 2) { xi = 1.0f / t;          ld = -2.0f * logf(fabsf(t)); }
                else if (sel == 3) { xi = (t - 5.0f) / 0.8f; ld = 0.22314355131420976f; }
                else if (sel == 4) {
                    float yc = fminf(fmaxf(t, 1e-6f), 1.0f - 1e-6f);
                    float la = logf(yc), lb = log1pf(-yc);
                    xi = la - lb;
                    ld = -la - lb;
                } else {
                    float yc = fmaxf(t, 1e-6f);
                    float em = expm1f(yc);
                    xi = logf(em);
                    ld = yc - xi;
                }
                xi = fminf(fmaxf(xi, -1e18f), 1e18f);   // never NaN
                loc[k] = xi;
                ap[k]  = (ld - LOGC_F) * LOG2E_F;       // fold Jacobian + normalizer
                mnv = fminf(mnv, xi); mxv = fmaxf(mxv, xi);
                apm = fmaxf(apm, ap[k]);
                acc[k] = 0.0f;
            }
            bias = ap[0];   // constant across k for affine sels (used only if chain)
        }
        mnv = wredmin(mnv); mxv = wredmax(mxv);
        if (!phA) apm = wredmax(apm);

        // underflow margin
        const float margin = phA
            ? (sqrtf((CUT_F + A_CONST) * INVK_F) + SLACK_F)
            : (sqrtf(fmaxf(CUT_F + apm, 0.0f) * INVK_F) + SLACK_F);
        int lo = 0, hi = NX;
        if (ok) {
            lo = lbound(xsort, mnv - margin) - 2; if (lo < 0) lo = 0;
            hi = lbound(xsort, mxv + margin) + 2; if (hi > NX) hi = NX;
        }

        // geometric-recurrence chain over 8 uniformly spaced points:
        //   step exponent at k: c1*d + (2k+1)*c2, k=0..6 -> bound with 15|c2|
        const float sp  = (phA ? dsA : alpha * dsB) * GSTEP_F;
        const float c1  = K2F2 * sp;
        const float c2  = K2F * sp * sp;
        const float c3  = 2.0f * c2;
        const float dmx = (mxv - mnv) + margin;
        const bool chain = ok && uniform &&
            (fabsf(c1) * dmx + 15.0f * fabsf(c2) < 120.0f) && (fabsf(c3) < 120.0f);

        if (chain) {
            const float sig = ex2f(c3);
            const float l0  = loc[0];
            #pragma unroll 2
            for (int i = lo; i < hi; i++) {
                const float x = xsort[i];
                const float d = l0 - x;
                float t = ex2f(fmaf(K2F * d, d, bias));
                float u = ex2f(fminf(fmaf(c1, d, c2), 125.0f));
                acc[0] += t;
                #pragma unroll
                for (int k = 1; k < 8; k++) {
                    t *= u; acc[k] += t; u *= sig;
                }
            }
        } else {
            #pragma unroll 1
            for (int i = lo; i < hi; i++) {
                const float x = xsort[i];
                #pragma unroll
                for (int k = 0; k < 8; k++) {
                    float d = loc[k] - x;
                    acc[k] += ex2f(fmaf(K2F * d, d, ap[k]));
                }
            }
        }

        // ---- write out: A -> slot 0, B -> slot 1 (with slot_idx override) ----
        if (phA) {
            #pragma unroll
            for (int k = 0; k < 8; k++) {
                const int j = wp * 256 + k * 32 + l;
                const float prev = (slot == 0) ? bank[rowo + j] : 0.0f;
                out[rowo + j] = (slot == 0) ? prev : acc[k];
            }
        } else {
            #pragma unroll
            for (int k = 0; k < 8; k++) {
                const int j = wp * 256 + k * 32 + l;
                const float prev = (slot == 1) ? bank[rowo + j] : 0.0f;
                out[SLOT_ELEMS + rowo + j] = (slot == 1) ? prev : acc[k];
            }
        }
    } else {
        // ================= COPY PATH: slots 2..127 =================
        // out[k] = bank[k] except out[slot] = bank[0]
        const int copyIdx = (bid < COPY_HEAD) ? bid : (bid - NROWS);  // dense 0..NCOPY-1
        const float4* __restrict__ src4 = (const float4*)bank;
        float4* __restrict__ dst4 = (float4*)out;
        const unsigned perSlot4 = SLOT_ELEMS / 4;          // 131072 = 2^17
        // contiguous per-block range: [copyIdx*1792, +1792) float4 (28 KB)
        const unsigned base = (unsigned)copyIdx * BLK_RANGE + tid;

        float4 vals[PER_THREAD];
        size_t dofs[PER_THREAD];
        #pragma unroll
        for (int u = 0; u < PER_THREAD; u++) {
            const unsigned vv = base + (unsigned)u * THREADS;
            const unsigned sp2 = vv >> 17, within = vv & (perSlot4 - 1);
            const int dstSlot = (int)sp2 + 2;
            const int srcSlot = (dstSlot == slot) ? 0 : dstSlot;
            dofs[u] = (size_t)dstSlot * perSlot4 + within;
            vals[u] = __ldcs(src4 + (size_t)srcSlot * perSlot4 + within);
        }
        #pragma unroll
        for (int u = 0; u < PER_THREAD; u++) {
            __stcs(dst4 + dofs[u], vals[u]);
        }
    }
}

extern "C" void kernel_launch(void* const* d_in, const int* in_sizes, int n_in,
                              void* d_out, int out_size)
{
    const float* inputs   = (const float*)d_in[0];  // (256, 512)
    const float* bank     = (const float*)d_in[1];  // (128, 512, 1024)
    const float* noise    = (const float*)d_in[2];  // (512, 2048)
    const int*   comp     = (const int*)  d_in[3];  // (512, 2048)
    const int*   sel      = (const int*)  d_in[4];  // (512)
    const int*   slot_idx = (const int*)  d_in[5];  // scalar

    kde_fused_kernel<<<GRID_BLOCKS, THREADS>>>(
        inputs, bank, noise, comp, sel, slot_idx, (float*)d_out);
}

// round 17
// speedup vs baseline: 1.0593x; 1.0593x over previous
#include <cuda_runtime.h>
#include <cstdint>

// Problem constants (fixed shapes)
#define THREADS      256
#define NROWS        512
#define NX           256
#define NQ           2048
#define RGRID        1024
#define SLOT_ELEMS   (NROWS * RGRID)      // 524288 floats per slot
#define NCOPY        9216                 // copy blocks (256 thr x 7 float4 each, exact)
#define COPY_HEAD    1024                 // copy blocks placed before compute blocks
#define GRID_BLOCKS  (NCOPY + NROWS)      // 9728
#define PER_THREAD   7                    // float4 per copy thread (exact division)
#define BLK_RANGE    (THREADS * PER_THREAD) // 1792 float4 = 28 KB contiguous per block

// math constants
#define K2F      (-72.13475204444817f)   /* -50 * log2(e) : exp(-50 d^2) = 2^(K2F*d^2) */
#define K2F2     (-144.26950408889634f)  /* 2 * K2F */
#define LOGC_F   (4.161530884690189f)    /* log(256) + log(0.1) + log(sqrt(2pi)) */
#define LOG2E_F  (1.4426950408889634f)
#define A_CONST  ((float)(-4.161530884690189 * 1.4426950408889634))  /* bias for phase A */
#define CUT_F    (160.0f)                /* very conservative: past denormal floor (-149) */
#define INVK_F   (0.013862943611198906f) /* 1 / 72.1347... = ln2/50 */
#define SLACK_F  (0.1f)                  /* absolute margin slack */
#define GSTEP_F  (0.03128054740957967f)  /* 32/1023 */

__device__ __forceinline__ float ex2f(float a) {
    float r;
    asm("ex2.approx.f32 %0, %1;" : "=f"(r) : "f"(a));
    return r;
}

__device__ __forceinline__ float wredmin(float v) {
    #pragma unroll
    for (int o = 16; o; o >>= 1) v = fminf(v, __shfl_xor_sync(0xffffffffu, v, o));
    return v;
}
__device__ __forceinline__ float wredmax(float v) {
    #pragma unroll
    for (int o = 16; o; o >>= 1) v = fmaxf(v, __shfl_xor_sync(0xffffffffu, v, o));
    return v;
}

// lower_bound over 256 sorted floats (branchless, 8 steps)
__device__ __forceinline__ int lbound(const float* __restrict__ xs, float v) {
    int p = 0;
    #pragma unroll
    for (int s = 128; s; s >>= 1)
        if (xs[p + s - 1] < v) p += s;
    return p;
}

__global__ __launch_bounds__(THREADS)
void kde_fused_kernel(
    const float* __restrict__ inputs,   // (256, 512)
    const float* __restrict__ bank,     // (128, 512, 1024)
    const float* __restrict__ noise,    // (512, 2048)
    const int*   __restrict__ comp,     // (512, 2048)
    const int*   __restrict__ sel_arr,  // (512)
    const int*   __restrict__ slot_ptr, // (1)
    float*       __restrict__ out)      // (128, 512, 1024)
{
    const int bid = blockIdx.x;
    const int tid = threadIdx.x;
    const int slot = slot_ptr[0];

    // Block placement (the R11/R14 layout -- best measured):
    //   [0, COPY_HEAD)                : copy (wave 1 saturates DRAM from t=0)
    //   [COPY_HEAD, COPY_HEAD+NROWS)  : compute (one confined band mid-kernel)
    //   [COPY_HEAD+NROWS, GRID_BLOCKS): copy (no compute tail)
    const bool is_compute = (bid >= COPY_HEAD) && (bid < COPY_HEAD + NROWS);

    if (is_compute) {
        // ============ COMPUTE PATH: one block per row ============
        const int r = bid - COPY_HEAD;
        __shared__ float xsh[NX];     // original order (for comp indexing)
        __shared__ float xsort[NX];   // sorted ascending (for range-culled sums)
        __shared__ float red[4][8];
        __shared__ int   sortok;

        const float xval = inputs[(size_t)tid * NROWS + r];
        xsh[tid]   = xval;
        xsort[tid] = xval;
        if (tid == 0) sortok = 1;
        __syncthreads();

        const int sel = sel_arr[r];

        // ---- per-row min/max of samples s and transformed y over 2048 q ----
        float smn = 3.4e38f, smx = -3.4e38f, ymn = 3.4e38f, ymx = -3.4e38f;
        const size_t rowq = (size_t)r * NQ;
        for (int q = tid; q < NQ; q += THREADS) {
            int   c = comp[rowq + q];
            float s = fmaf(0.1f, noise[rowq + q], xsh[c]);
            smn = fminf(smn, s);
            smx = fmaxf(smx, s);
            float y;
            if (sel == 0)      y = 2.0f * s;
            else if (sel == 1) y = s - 3.0f;
            else if (sel == 2) { float ss = (fabsf(s) < 1e-6f) ? 1e-6f : s; y = 1.0f / ss; }
            else if (sel == 3) y = 0.8f * s + 5.0f;
            else if (sel == 4) y = 1.0f / (1.0f + expf(-s));                        // sigmoid
            else               y = fmaxf(s, 0.0f) + log1pf(expf(-fabsf(s)));        // softplus
            ymn = fminf(ymn, y);
            ymx = fmaxf(ymx, y);
        }
        smn = wredmin(smn); smx = wredmax(smx);
        ymn = wredmin(ymn); ymx = wredmax(ymx);
        const int w = tid >> 5, l = tid & 31;
        if (l == 0) { red[0][w] = smn; red[1][w] = smx; red[2][w] = ymn; red[3][w] = ymx; }
        __syncthreads();
        smn = red[0][0]; smx = red[1][0]; ymn = red[2][0]; ymx = red[3][0];
        #pragma unroll
        for (int ww = 1; ww < 8; ww++) {
            smn = fminf(smn, red[0][ww]); smx = fmaxf(smx, red[1][ww]);
            ymn = fminf(ymn, red[2][ww]); ymx = fmaxf(ymx, red[3][ww]);
        }
        __syncthreads();  // everyone done reading red before sort mutates shared state

        // ---- bitonic sort xsort ascending (256 elements, 1 per thread) ----
        for (int kk = 2; kk <= NX; kk <<= 1) {
            for (int jj = kk >> 1; jj > 0; jj >>= 1) {
                int ixj = tid ^ jj;
                if (ixj > tid) {
                    float a = xsort[tid], b = xsort[ixj];
                    bool up = ((tid & kk) == 0);
                    if (up ? (a > b) : (a < b)) { xsort[tid] = b; xsort[ixj] = a; }
                }
                __syncthreads();
            }
        }

        // ---- verify sortedness; on any violation fall back to full range.
        if (tid < NX - 1) {
            if (xsort[tid] > xsort[tid + 1]) sortok = 0;  // benign write race
        }
        __syncthreads();
        const bool ok = (sortok != 0);

        const float dsA = smx - smn;
        const float dsB = ymx - ymn;
        const size_t rowo = (size_t)r * RGRID;

        // ================= PHASE A: raw grid density (slot 0) =================
        {
            float loc[4], acc[4];
            float mnv = 3.4e38f, mxv = -3.4e38f;
            #pragma unroll
            for (int k = 0; k < 4; k++) {
                const int j = w * 128 + k * 32 + l;
                float tA = smn + dsA * ((float)j / 1023.0f);
                if (tA == 0.0f) tA = 1e-7f;
                loc[k] = tA;
                mnv = fminf(mnv, tA); mxv = fmaxf(mxv, tA);
                acc[k] = 0.0f;
            }
            mnv = wredmin(mnv); mxv = wredmax(mxv);
            // analytic chunk bounds (loc monotonic in j up to the zero-substitution)
            {
                float aLo = smn + dsA * ((float)(w * 128) / 1023.0f);
                float aHi = smn + dsA * ((float)(w * 128 + 127) / 1023.0f);
                mnv = fminf(mnv, fminf(aLo, aHi));
                mxv = fmaxf(mxv, fmaxf(aLo, aHi));
            }
            const float margin = sqrtf((CUT_F + A_CONST) * INVK_F) + SLACK_F;
            int lo = 0, hi = NX;
            if (ok) {
                lo = lbound(xsort, mnv - margin) - 2; if (lo < 0) lo = 0;
                hi = lbound(xsort, mxv + margin) + 2; if (hi > NX) hi = NX;
            }
            // geometric-recurrence fast path (uniform spacing s)
            const float sA  = dsA * GSTEP_F;
            const float c1  = K2F2 * sA;
            const float c2  = K2F * sA * sA;
            const float c3  = 2.0f * c2;
            const float dmx = (mxv - mnv) + margin;
            const bool chain = ok &&
                (fabsf(c1) * dmx + fabsf(c2) < 120.0f) && (fabsf(c3) < 120.0f);
            if (chain) {
                const float sig = ex2f(c3);
                const float l0  = loc[0];
                #pragma unroll 2
                for (int i = lo; i < hi; i++) {
                    const float x = xsort[i];
                    const float d = l0 - x;
                    float t = ex2f(fmaf(K2F * d, d, A_CONST));
                    float u = ex2f(fminf(fmaf(c1, d, c2), 125.0f));
                    acc[0] += t;
                    t *= u; acc[1] += t; u *= sig;
                    t *= u; acc[2] += t; u *= sig;
                    t *= u; acc[3] += t;
                }
            } else {
                #pragma unroll 2
                for (int i = lo; i < hi; i++) {
                    const float x = xsort[i];
                    #pragma unroll
                    for (int k = 0; k < 4; k++) {
                        float d = loc[k] - x;
                        acc[k] += ex2f(fmaf(K2F * d, d, A_CONST));
                    }
                }
            }
            #pragma unroll
            for (int k = 0; k < 4; k++) {
                const int j = w * 128 + k * 32 + l;
                const float prev = (slot == 0) ? bank[rowo + j] : 0.0f;
                out[rowo + j] = (slot == 0) ? prev : acc[k];
            }
        }

        // ============ PHASE B: transformed grid density (slot 1) ============
        {
            float loc[4], ap[4], acc[4];
            float mnv = 3.4e38f, mxv = -3.4e38f, apm = -3.4e38f;
            #pragma unroll
            for (int k = 0; k < 4; k++) {
                const int j = w * 128 + k * 32 + l;
                float t = ymn + dsB * ((float)j / 1023.0f);
                if (t == 0.0f) t = 1e-7f;

                float xi, ld;
                if (sel == 0)      { xi = t * 0.5f;          ld = -0.6931471805599453f; }
                else if (sel == 1) { xi = t + 3.0f;          ld = 0.0f; }
                else if (sel == 2) { xi = 1.0f / t;          ld = -2.0f * logf(fabsf(t)); }
                else if (sel == 3) { xi = (t - 5.0f) / 0.8f; ld = 0.22314355131420976f; }
                else if (sel == 4) {
                    float yc = fminf(fmaxf(t, 1e-6f), 1.0f - 1e-6f);
                    float la = logf(yc), lb = log1pf(-yc);
                    xi = la - lb;
                    ld = -la - lb;
                } else {
                    float yc = fmaxf(t, 1e-6f);
                    float em = expm1f(yc);
                    xi = logf(em);
                    ld = yc - xi;
                }
                xi = fminf(fmaxf(xi, -1e18f), 1e18f);   // never NaN
                loc[k] = xi;
                ap[k]  = (ld - LOGC_F) * LOG2E_F;       // fold Jacobian + normalizer
                mnv = fminf(mnv, xi); mxv = fmaxf(mxv, xi);
                apm = fmaxf(apm, ap[k]);
                acc[k] = 0.0f;
            }
            mnv = wredmin(mnv); mxv = wredmax(mxv); apm = wredmax(apm);
            const float margin = sqrtf(fmaxf(CUT_F + apm, 0.0f) * INVK_F) + SLACK_F;
            int lo = 0, hi = NX;
            if (ok) {
                lo = lbound(xsort, mnv - margin) - 2; if (lo < 0) lo = 0;
                hi = lbound(xsort, mxv + margin) + 2; if (hi > NX) hi = NX;
            }
            // chain path only for affine transforms (uniform xi spacing, const ld)
            const bool affine = (sel == 0) | (sel == 1) | (sel == 3);
            const float alpha = (sel == 0) ? 0.5f : ((sel == 3) ? 1.25f : 1.0f);
            const float sB  = alpha * dsB * GSTEP_F;
            const float c1  = K2F2 * sB;
            const float c2  = K2F * sB * sB;
            const float c3  = 2.0f * c2;
            const float dmx = (mxv - mnv) + margin;
            const bool chain = ok && affine &&
                (fabsf(c1) * dmx + fabsf(c2) < 120.0f) && (fabsf(c3) < 120.0f);
            if (chain) {
                const float sig = ex2f(c3);
                const float l0  = loc[0];
                const float apc = ap[0];    // ld constant across k for affine sels
                #pragma unroll 2
                for (int i = lo; i < hi; i++) {
                    const float x = xsort[i];
                    const float d = l0 - x;
                    float t = ex2f(fmaf(K2F * d, d, apc));
                    float u = ex2f(fminf(fmaf(c1, d, c2), 125.0f));
                    acc[0] += t;
                    t *= u; acc[1] += t; u *= sig;
                    t *= u; acc[2] += t; u *= sig;
                    t *= u; acc[3] += t;
                }
            } else {
                #pragma unroll 2
                for (int i = lo; i < hi; i++) {
                    const float x = xsort[i];
                    #pragma unroll
                    for (int k = 0; k < 4; k++) {
                        float d = loc[k] - x;
                        acc[k] += ex2f(fmaf(K2F * d, d, ap[k]));
                    }
                }
            }
            #pragma unroll
            for (int k = 0; k < 4; k++) {
                const int j = w * 128 + k * 32 + l;
                const float prev = (slot == 1) ? bank[rowo + j] : 0.0f;
                out[SLOT_ELEMS + rowo + j] = (slot == 1) ? prev : acc[k];
            }
        }
    } else {
        // ================= COPY PATH: slots 2..127 =================
        // out[k] = bank[k] except out[slot] = bank[0]
        const int copyIdx = (bid < COPY_HEAD) ? bid : (bid - NROWS);  // dense 0..NCOPY-1
        const float4* __restrict__ src4 = (const float4*)bank;
        float4* __restrict__ dst4 = (float4*)out;
        const unsigned perSlot4 = SLOT_ELEMS / 4;          // 131072 = 2^17
        // contiguous per-block range: [copyIdx*1792, +1792) float4 (28 KB)
        const unsigned base = (unsigned)copyIdx * BLK_RANGE + tid;

        float4 vals[PER_THREAD];
        size_t dofs[PER_THREAD];
        #pragma unroll
        for (int u = 0; u < PER_THREAD; u++) {
            const unsigned vv = base + (unsigned)u * THREADS;
            const unsigned sp = vv >> 17, within = vv & (perSlot4 - 1);
            const int dstSlot = (int)sp + 2;
            const int srcSlot = (dstSlot == slot) ? 0 : dstSlot;
            dofs[u] = (size_t)dstSlot * perSlot4 + within;
            vals[u] = __ldcs(src4 + (size_t)srcSlot * perSlot4 + within);
        }
        #pragma unroll
        for (int u = 0; u < PER_THREAD; u++) {
            __stcs(dst4 + dofs[u], vals[u]);
        }
    }
}

extern "C" void kernel_launch(void* const* d_in, const int* in_sizes, int n_in,
                              void* d_out, int out_size)
{
    const float* inputs   = (const float*)d_in[0];  // (256, 512)
    const float* bank     = (const float*)d_in[1];  // (128, 512, 1024)
    const float* noise    = (const float*)d_in[2];  // (512, 2048)
    const int*   comp     = (const int*)  d_in[3];  // (512, 2048)
    const int*   sel      = (const int*)  d_in[4];  // (512)
    const int*   slot_idx = (const int*)  d_in[5];  // scalar

    kde_fused_kernel<<<GRID_BLOCKS, THREADS>>>(
        inputs, bank, noise, comp, sel, slot_idx, (float*)d_out);
}